// round 3
// baseline (speedup 1.0000x reference)
#include <cuda_runtime.h>
#include <cstdint>

// HardNegativeMining: per-row top-k (k = 128) of logits with the one-hot
// positive boosted to rank 0. Output = concat(out_logits[B,128], out_labels[B,128]).
//
// Strategy: one CTA per row. Single streaming pass collects all elements
// above a static threshold T1 (data is N(0,1); E[count]=~347 per 100k) into a
// shared candidate buffer of packed 64-bit keys, then a bitonic sort ranks
// them. A histogram-based fallback guarantees correctness if the static
// threshold ever fails (count < 128 or buffer overflow).

#define N_CAND   100000
#define K_OUT    128
#define THREADS  512
#define CAP      2048
#define SORT_P   2048
#define NBINS    2048      // top 11 bits of the orderable key
#define T1       2.7f

// monotone float -> uint transform (ascending)
__device__ __forceinline__ unsigned int f2k(float f) {
    unsigned int u = __float_as_uint(f);
    return (u & 0x80000000u) ? ~u : (u | 0x80000000u);
}
__device__ __forceinline__ float k2f(unsigned int k) {
    unsigned int u = (k & 0x80000000u) ? (k & 0x7FFFFFFFu) : ~k;
    return __uint_as_float(u);
}

__device__ __forceinline__ unsigned long long pack(unsigned int key, int idx) {
    // high 32: key (descending primary). low 32: ~idx so that equal keys
    // sort with the SMALLER index first under a descending sort (JAX tie-break).
    return ((unsigned long long)key << 32) | (unsigned int)(~idx);
}

__global__ __launch_bounds__(THREADS, 4)
void hnm_topk_kernel(const float* __restrict__ logits,
                     const float* __restrict__ labels,
                     float* __restrict__ out_logits,
                     float* __restrict__ out_labels) {
    __shared__ unsigned long long cand[SORT_P];   // 16 KB
    __shared__ unsigned int hist[NBINS];          // 8 KB (fallback only)
    __shared__ int   s_cnt;
    __shared__ int   s_pos;
    __shared__ float s_posval;
    __shared__ int   s_binthr;

    const int row = blockIdx.x;
    const int tid = threadIdx.x;

    if (tid == 0) { s_cnt = 0; s_pos = -1; s_posval = 0.0f; }
    __syncthreads();

    const float4* lg4 = reinterpret_cast<const float4*>(logits + (size_t)row * N_CAND);
    const float4* lb4 = reinterpret_cast<const float4*>(labels + (size_t)row * N_CAND);
    const int NV = N_CAND / 4;   // 25000

    // ---- Pass 1: fused stream of logits + labels (the only mandatory DRAM read)
    for (int v = tid; v < NV; v += THREADS) {
        float4 x = lg4[v];
        float4 l = lb4[v];
        int base = v * 4;

        float xs0 = x.x, xs1 = x.y, xs2 = x.z, xs3 = x.w;
        float ls0 = l.x, ls1 = l.y, ls2 = l.z, ls3 = l.w;

        // candidate / positive handling (rare branches)
        if (ls0 != 0.0f) { s_pos = base + 0; s_posval = xs0;
            int p = atomicAdd(&s_cnt, 1); if (p < CAP) cand[p] = pack(0xFFFFFFFFu, base + 0);
        } else if (xs0 > T1) {
            int p = atomicAdd(&s_cnt, 1); if (p < CAP) cand[p] = pack(f2k(xs0), base + 0);
        }
        if (ls1 != 0.0f) { s_pos = base + 1; s_posval = xs1;
            int p = atomicAdd(&s_cnt, 1); if (p < CAP) cand[p] = pack(0xFFFFFFFFu, base + 1);
        } else if (xs1 > T1) {
            int p = atomicAdd(&s_cnt, 1); if (p < CAP) cand[p] = pack(f2k(xs1), base + 1);
        }
        if (ls2 != 0.0f) { s_pos = base + 2; s_posval = xs2;
            int p = atomicAdd(&s_cnt, 1); if (p < CAP) cand[p] = pack(0xFFFFFFFFu, base + 2);
        } else if (xs2 > T1) {
            int p = atomicAdd(&s_cnt, 1); if (p < CAP) cand[p] = pack(f2k(xs2), base + 2);
        }
        if (ls3 != 0.0f) { s_pos = base + 3; s_posval = xs3;
            int p = atomicAdd(&s_cnt, 1); if (p < CAP) cand[p] = pack(0xFFFFFFFFu, base + 3);
        } else if (xs3 > T1) {
            int p = atomicAdd(&s_cnt, 1); if (p < CAP) cand[p] = pack(f2k(xs3), base + 3);
        }
    }
    __syncthreads();

    int cnt = s_cnt;

    // ---- Fallback (correctness guard; ~never taken for N(0,1) inputs).
    // If the static threshold captured too few (<128) or overflowed the
    // buffer, redo selection with an exact 11-bit histogram threshold.
    if (cnt < K_OUT || cnt > CAP) {
        for (int b = tid; b < NBINS; b += THREADS) hist[b] = 0;
        __syncthreads();

        for (int v = tid; v < NV; v += THREADS) {
            float4 x = lg4[v];
            int base = v * 4;
            float xs[4] = {x.x, x.y, x.z, x.w};
            #pragma unroll
            for (int c = 0; c < 4; c++) {
                unsigned int k = (base + c == s_pos) ? 0xFFFFFFFFu : f2k(xs[c]);
                atomicAdd(&hist[k >> 21], 1u);
            }
        }
        __syncthreads();

        if (tid == 0) {
            unsigned int acc = 0; int b = NBINS - 1;
            for (; b > 0; b--) { acc += hist[b]; if (acc >= K_OUT) break; }
            s_binthr = b;
            s_cnt = 0;
        }
        __syncthreads();

        unsigned int kth = (unsigned int)s_binthr << 21;
        for (int v = tid; v < NV; v += THREADS) {
            float4 x = lg4[v];
            int base = v * 4;
            float xs[4] = {x.x, x.y, x.z, x.w};
            #pragma unroll
            for (int c = 0; c < 4; c++) {
                unsigned int k = (base + c == s_pos) ? 0xFFFFFFFFu : f2k(xs[c]);
                if (k >= kth) {
                    int p = atomicAdd(&s_cnt, 1);
                    if (p < CAP) cand[p] = pack(k, base + c);
                }
            }
        }
        __syncthreads();
        cnt = min(s_cnt, CAP);
    }

    // ---- Pad then bitonic-sort (ascending; read from the top afterwards)
    for (int i = cnt + tid; i < SORT_P; i += THREADS) cand[i] = 0ull;
    __syncthreads();

    for (int k = 2; k <= SORT_P; k <<= 1) {
        for (int j = k >> 1; j > 0; j >>= 1) {
            for (int i = tid; i < SORT_P; i += THREADS) {
                int ixj = i ^ j;
                if (ixj > i) {
                    unsigned long long a = cand[i];
                    unsigned long long b = cand[ixj];
                    bool up = ((i & k) == 0);
                    if ((a > b) == up) { cand[i] = b; cand[ixj] = a; }
                }
            }
            __syncthreads();
        }
    }

    // ---- Emit top-128 (descending). Values reconstructed bit-exactly from keys.
    if (tid < K_OUT) {
        unsigned long long e = cand[SORT_P - 1 - tid];
        unsigned int key = (unsigned int)(e >> 32);
        float val, lab;
        if (key == 0xFFFFFFFFu) { val = s_posval; lab = 1.0f; }
        else                    { val = k2f(key); lab = 0.0f; }
        out_logits[(size_t)row * K_OUT + tid] = val;
        out_labels[(size_t)row * K_OUT + tid] = lab;
    }
}

extern "C" void kernel_launch(void* const* d_in, const int* in_sizes, int n_in,
                              void* d_out, int out_size) {
    const float* logits = (const float*)d_in[0];
    const float* labels = (const float*)d_in[1];
    // d_in[2] = num_hard_negatives (127) — k=128 is compiled in.

    const int B = in_sizes[0] / N_CAND;   // 2048
    float* out_logits = (float*)d_out;
    float* out_labels = out_logits + (size_t)B * K_OUT;

    hnm_topk_kernel<<<B, THREADS>>>(logits, labels, out_logits, out_labels);
}

// round 4
// speedup vs baseline: 1.5215x; 1.5215x over previous
#include <cuda_runtime.h>
#include <cstdint>

// HardNegativeMining: per-row top-128 of logits with the one-hot positive
// boosted to rank 0. Output = concat(out_logits[B,128], out_labels[B,128]).
//
// One CTA per row. Streaming pass (only mandatory DRAM traffic: logits+labels,
// 1.6 GB total) collects elements > T1 into a 512-entry candidate buffer of
// packed 64-bit keys; a register-resident hybrid bitonic sort (shfl for
// intra-warp stages, smem only for cross-warp) ranks them. Histogram fallback
// guards the (astronomically unlikely) static-threshold failure.

#define N_CAND   100000
#define K_OUT    128
#define THREADS  512
#define CAP      512        // mean count ~347, sd ~19 -> overflow at +8.9 sigma
#define SORT_P   512
#define NBINS    2048
#define T1       2.7f

__device__ __forceinline__ unsigned int f2k(float f) {
    unsigned int u = __float_as_uint(f);
    return (u & 0x80000000u) ? ~u : (u | 0x80000000u);
}
__device__ __forceinline__ float k2f(unsigned int k) {
    unsigned int u = (k & 0x80000000u) ? (k & 0x7FFFFFFFu) : ~k;
    return __uint_as_float(u);
}
__device__ __forceinline__ unsigned long long pack(unsigned int key, int idx) {
    // high 32: key (value, ascending transform). low 32: ~idx so equal keys
    // rank smaller index first under a descending read-out (JAX tie-break).
    return ((unsigned long long)key << 32) | (unsigned int)(~idx);
}

struct SRow {
    unsigned long long cand[SORT_P];   // 4 KB
    unsigned int hist[NBINS];          // 8 KB (fallback only)
    int   cnt;
    int   pos;
    float posval;
    int   binthr;
};

__device__ __forceinline__ void handle4(const float4& x, const float4& l,
                                        int base, SRow* s) {
    // fast reject: no label bit set AND all four logits below threshold
    unsigned int l0 = __float_as_uint(l.x) | __float_as_uint(l.y)
                    | __float_as_uint(l.z) | __float_as_uint(l.w);
    float mx = fmaxf(fmaxf(x.x, x.y), fmaxf(x.z, x.w));
    if (__builtin_expect((l0 == 0u) & (mx <= T1), 1)) return;

    const float xs[4] = {x.x, x.y, x.z, x.w};
    const float ls[4] = {l.x, l.y, l.z, l.w};
    #pragma unroll
    for (int c = 0; c < 4; c++) {
        if (ls[c] != 0.0f) {
            s->pos = base + c; s->posval = xs[c];
            int p = atomicAdd(&s->cnt, 1);
            if (p < CAP) s->cand[p] = pack(0xFFFFFFFFu, base + c);
        } else if (xs[c] > T1) {
            int p = atomicAdd(&s->cnt, 1);
            if (p < CAP) s->cand[p] = pack(f2k(xs[c]), base + c);
        }
    }
}

__global__ __launch_bounds__(THREADS, 4)
void hnm_topk_kernel(const float* __restrict__ logits,
                     const float* __restrict__ labels,
                     float* __restrict__ out_logits,
                     float* __restrict__ out_labels) {
    __shared__ SRow s;

    const int row = blockIdx.x;
    const int tid = threadIdx.x;

    if (tid == 0) { s.cnt = 0; s.pos = -1; s.posval = 0.0f; }
    __syncthreads();

    const float4* lg4 = reinterpret_cast<const float4*>(logits + (size_t)row * N_CAND);
    const float4* lb4 = reinterpret_cast<const float4*>(labels + (size_t)row * N_CAND);
    const int NV = N_CAND / 4;   // 25000

    // ---- Streaming pass: 2-way unrolled, loads front-batched for MLP
    int v = tid;
    for (; v + THREADS < NV; v += 2 * THREADS) {
        float4 xa = lg4[v];
        float4 xb = lg4[v + THREADS];
        float4 la = lb4[v];
        float4 lb = lb4[v + THREADS];
        handle4(xa, la, v * 4, &s);
        handle4(xb, lb, (v + THREADS) * 4, &s);
    }
    for (; v < NV; v += THREADS) {
        float4 x = lg4[v];
        float4 l = lb4[v];
        handle4(x, l, v * 4, &s);
    }
    __syncthreads();

    int cnt = s.cnt;

    // ---- Fallback: exact 11-bit histogram threshold (correctness guard,
    //      ~never taken for N(0,1) inputs).
    if (cnt < K_OUT || cnt > CAP) {
        for (int b = tid; b < NBINS; b += THREADS) s.hist[b] = 0;
        __syncthreads();

        for (int w = tid; w < NV; w += THREADS) {
            float4 x = lg4[w];
            int base = w * 4;
            float xs[4] = {x.x, x.y, x.z, x.w};
            #pragma unroll
            for (int c = 0; c < 4; c++) {
                unsigned int k = (base + c == s.pos) ? 0xFFFFFFFFu : f2k(xs[c]);
                atomicAdd(&s.hist[k >> 21], 1u);
            }
        }
        __syncthreads();

        if (tid == 0) {
            unsigned int acc = 0; int b = NBINS - 1;
            for (; b > 0; b--) {
                unsigned int nacc = acc + s.hist[b];
                if (nacc >= K_OUT && nacc <= CAP) { acc = nacc; b--; continue; }
                if (nacc >= K_OUT) break;         // stop before overflowing CAP
                acc = nacc;
            }
            // b+1 is the last bin fully included; threshold at bin boundary
            s.binthr = (acc >= K_OUT) ? (b + 1) : b;   // ensure >= K_OUT coverage
            if (acc < K_OUT) s.binthr = b;             // include bin b too
            s.cnt = 0;
        }
        __syncthreads();

        unsigned int kth = (unsigned int)s.binthr << 21;
        for (int w = tid; w < NV; w += THREADS) {
            float4 x = lg4[w];
            int base = w * 4;
            float xs[4] = {x.x, x.y, x.z, x.w};
            #pragma unroll
            for (int c = 0; c < 4; c++) {
                unsigned int k = (base + c == s.pos) ? 0xFFFFFFFFu : f2k(xs[c]);
                if (k >= kth) {
                    int p = atomicAdd(&s.cnt, 1);
                    if (p < CAP) s.cand[p] = pack(k, base + c);
                }
            }
        }
        __syncthreads();
        cnt = min(s.cnt, CAP);
    }

    // ---- Pad to SORT_P
    for (int i = cnt + tid; i < SORT_P; i += THREADS) s.cand[i] = 0ull;
    __syncthreads();

    // ---- Hybrid bitonic sort: 512 elements, 1 per thread.
    //      j < 32  -> shfl_xor (no smem, no barrier)
    //      j >= 32 -> smem exchange (2 barriers each; 10 such iterations)
    unsigned long long r = s.cand[tid];
    #pragma unroll
    for (int k = 2; k <= SORT_P; k <<= 1) {
        #pragma unroll
        for (int j = k >> 1; j > 0; j >>= 1) {
            unsigned long long other;
            if (j >= 32) {
                __syncthreads();
                s.cand[tid] = r;
                __syncthreads();
                other = s.cand[tid ^ j];
            } else {
                other = __shfl_xor_sync(0xFFFFFFFFu, r, j);
            }
            bool lower = (tid & j) == 0;
            bool up    = (tid & k) == 0;
            unsigned long long mn = (r < other) ? r : other;
            unsigned long long mx = (r < other) ? other : r;
            r = (lower == up) ? mn : mx;
        }
    }
    __syncthreads();
    s.cand[tid] = r;
    __syncthreads();

    // ---- Emit top-128 descending; values reconstructed bit-exactly.
    if (tid < K_OUT) {
        unsigned long long e = s.cand[SORT_P - 1 - tid];
        unsigned int key = (unsigned int)(e >> 32);
        float val, lab;
        if (key == 0xFFFFFFFFu) { val = s.posval; lab = 1.0f; }
        else                    { val = k2f(key); lab = 0.0f; }
        out_logits[(size_t)row * K_OUT + tid] = val;
        out_labels[(size_t)row * K_OUT + tid] = lab;
    }
}

extern "C" void kernel_launch(void* const* d_in, const int* in_sizes, int n_in,
                              void* d_out, int out_size) {
    const float* logits = (const float*)d_in[0];
    const float* labels = (const float*)d_in[1];
    const int B = in_sizes[0] / N_CAND;   // 2048
    float* out_logits = (float*)d_out;
    float* out_labels = out_logits + (size_t)B * K_OUT;

    hnm_topk_kernel<<<B, THREADS>>>(logits, labels, out_logits, out_labels);
}